// round 1
// baseline (speedup 1.0000x reference)
#include <cuda_runtime.h>
#include <math.h>

#define NQ    12
#define DIM   4096
#define BATCH 8
#define SEQ   64
#define BT    (BATCH*SEQ)
#define NTHR  256
#define PAIRS (DIM/2)
#define PPT   (PAIRS/NTHR)   // 8 pairs per thread
#define EPT   (DIM/NTHR)     // 16 elements per thread

#define PI_F 3.14159265358979323846

// scratch: QKV features [head][proj][bt][12]
__device__ float g_qkv[2*3*BT*12];

// ---- complex 2x2 gate on qubit q, in-place -------------------------------
__device__ __forceinline__ void apply_gate(float2* st, int q,
    float2 g00, float2 g01, float2 g10, float2 g11)
{
    const int tid = threadIdx.x;
    const int lom = (1 << q) - 1;
    #pragma unroll
    for (int k = 0; k < PPT; k++) {
        int p  = tid + k * NTHR;
        int i0 = ((p & ~lom) << 1) | (p & lom);
        int i1 = i0 | (1 << q);
        float2 s0 = st[i0], s1 = st[i1];
        float2 n0, n1;
        n0.x = g00.x*s0.x - g00.y*s0.y + g01.x*s1.x - g01.y*s1.y;
        n0.y = g00.x*s0.y + g00.y*s0.x + g01.x*s1.y + g01.y*s1.x;
        n1.x = g10.x*s0.x - g10.y*s0.y + g11.x*s1.x - g11.y*s1.y;
        n1.y = g10.x*s0.y + g10.y*s0.x + g11.x*s1.y + g11.y*s1.x;
        st[i0] = n0; st[i1] = n1;
    }
    __syncthreads();
}

// same gate, but reads src and writes dst (covers all 4096 amps -> acts as copy+gate)
__device__ __forceinline__ void apply_gate_src(float2* dst, const float2* src, int q,
    float2 g00, float2 g01, float2 g10, float2 g11)
{
    const int tid = threadIdx.x;
    const int lom = (1 << q) - 1;
    #pragma unroll
    for (int k = 0; k < PPT; k++) {
        int p  = tid + k * NTHR;
        int i0 = ((p & ~lom) << 1) | (p & lom);
        int i1 = i0 | (1 << q);
        float2 s0 = src[i0], s1 = src[i1];
        float2 n0, n1;
        n0.x = g00.x*s0.x - g00.y*s0.y + g01.x*s1.x - g01.y*s1.y;
        n0.y = g00.x*s0.y + g00.y*s0.x + g01.x*s1.y + g01.y*s1.x;
        n1.x = g10.x*s0.x - g10.y*s0.y + g11.x*s1.x - g11.y*s1.y;
        n1.y = g10.x*s0.y + g10.y*s0.x + g11.x*s1.y + g11.y*s1.x;
        dst[i0] = n0; dst[i1] = n1;
    }
    __syncthreads();
}

// CX(control c, target t): in-place swap of (i, i^2^t) where bit c of i is 1
__device__ __forceinline__ void apply_cx(float2* st, int c, int t)
{
    const int tid = threadIdx.x;
    const int lo  = (c < t) ? c : t;
    const int hi  = (c < t) ? t : c;
    const int lomask = (1 << lo) - 1;
    const int himask = (1 << hi) - 1;
    #pragma unroll
    for (int k = 0; k < 4; k++) {
        int p = tid + k * NTHR;                 // 10 free bits
        int i = ((p & ~lomask) << 1) | (p & lomask);   // make room at lo
        i     = ((i & ~himask) << 1) | (i & himask);   // make room at hi
        i    |= (1 << c);                       // control=1, target bit stays 0
        int j = i | (1 << t);
        float2 a = st[i];
        st[i] = st[j];
        st[j] = a;
    }
    __syncthreads();
}

// CZ layer: sign flip where popc(d & (d>>1) & mask) is odd
__device__ __forceinline__ void apply_cz(float2* st, unsigned mask)
{
    const int tid = threadIdx.x;
    #pragma unroll
    for (int k = 0; k < EPT; k++) {
        int d = tid + k * NTHR;
        unsigned m = ((unsigned)d & ((unsigned)d >> 1)) & mask;
        if (__popc(m) & 1) { st[d].x = -st[d].x; st[d].y = -st[d].y; }
    }
    __syncthreads();
}

// fused RY(theta) followed by RZ(phi) 2x2 gate
__device__ __forceinline__ void ryrz_gate(float th, float ph,
    float2& g00, float2& g01, float2& g10, float2& g11)
{
    float s, c, sh, ch;
    sincosf(0.5f * th, &s, &c);
    sincosf(0.5f * ph, &sh, &ch);
    g00 = make_float2( c * ch, -c * sh);
    g01 = make_float2(-s * ch,  s * sh);
    g10 = make_float2( s * ch,  s * sh);
    g11 = make_float2( c * ch,  c * sh);
}

extern __shared__ float2 smem_state[];

__global__ void __launch_bounds__(NTHR) qtf_main(
    const float* __restrict__ seq,
    const float* __restrict__ resp,
    const float* __restrict__ headp)
{
    float2* enc  = smem_state;
    float2* work = smem_state + DIM;
    const int bt  = blockIdx.x;
    const int t   = bt & (SEQ - 1);
    const int tid = threadIdx.x;
    const float x = seq[bt];

    // init |+...+> like uniform state 1/sqrt(4096) = 1/64
    #pragma unroll
    for (int k = 0; k < EPT; k++)
        enc[tid + k * NTHR] = make_float2(0.015625f, 0.0f);
    __syncthreads();

    // ---------------- encode: fused RY/RZ per qubit ----------------
    for (int i = 0; i < NQ; i++) {
        float th = x * (float)(PI_F * (double)(i + 1) / 12.0);
        float ph = x * (float)(PI_F / (double)(i + 1));
        float2 g00, g01, g10, g11;
        ryrz_gate(th, ph, g00, g01, g10, g11);
        apply_gate(enc, i, g00, g01, g10, g11);
    }
    // CX ladder + ring
    for (int i = 0; i < NQ - 1; i++) apply_cx(enc, i, i + 1);
    apply_cx(enc, NQ - 1, 0);

    // ---------------- reservoir layers ----------------
    for (int layer = 0; layer < 3; layer++) {
        for (int i = 0; i < NQ; i++) {
            float tt = resp[(layer * NQ + i) * 3 + 0];
            float pp = resp[(layer * NQ + i) * 3 + 1];
            float ll = resp[(layer * NQ + i) * 3 + 2];
            float st_, ct, sl, cl, sp, cp, spl, cpl;
            sincosf(0.5f * tt, &st_, &ct);
            sincosf(ll, &sl, &cl);
            sincosf(pp, &sp, &cp);
            sincosf(pp + ll, &spl, &cpl);
            float2 g00 = make_float2(ct, 0.0f);
            float2 g01 = make_float2(-cl * st_, -sl * st_);
            float2 g10 = make_float2( cp * st_,  sp * st_);
            float2 g11 = make_float2(cpl * ct,  spl * ct);
            apply_gate(enc, i, g00, g01, g10, g11);
        }
        apply_cz(enc, (layer & 1) ? 0x2AAu : 0x555u);
        apply_cx(enc, 0, NQ - 1);
    }

    // ---------------- projections (Q only needed at t = SEQ-1) ----------------
    for (int h = 0; h < 2; h++) {
        for (int p = 0; p < 3; p++) {
            if (p == 0 && t != SEQ - 1) continue;
            const float* pars = headp + (h * 3 + p) * (NQ * 2 * 2);
            for (int layer = 0; layer < 2; layer++) {
                for (int i = 0; i < NQ; i++) {
                    int k = (layer * NQ + i) * 2;
                    float2 g00, g01, g10, g11;
                    ryrz_gate(pars[k], pars[k + 1], g00, g01, g10, g11);
                    if (layer == 0 && i == 0)
                        apply_gate_src(work, enc, i, g00, g01, g10, g11);
                    else
                        apply_gate(work, i, g00, g01, g10, g11);
                }
                for (int i = 0; i < NQ - 1; i++) apply_cx(work, i, i + 1);
            }
            // features: <Z_q> for q=0..11 uses bit (11-q)
            float acc[NQ];
            #pragma unroll
            for (int q = 0; q < NQ; q++) acc[q] = 0.0f;
            #pragma unroll
            for (int k = 0; k < EPT; k++) {
                int d = tid + k * NTHR;
                float2 a = work[d];
                float pr = a.x * a.x + a.y * a.y;
                #pragma unroll
                for (int q = 0; q < NQ; q++)
                    acc[q] += ((d >> (NQ - 1 - q)) & 1) ? -pr : pr;
            }
            #pragma unroll
            for (int q = 0; q < NQ; q++)
                for (int off = 16; off; off >>= 1)
                    acc[q] += __shfl_xor_sync(0xffffffffu, acc[q], off);
            __shared__ float red[NQ];
            if (tid < NQ) red[tid] = 0.0f;
            __syncthreads();
            if ((tid & 31) == 0) {
                #pragma unroll
                for (int q = 0; q < NQ; q++) atomicAdd(&red[q], acc[q]);
            }
            __syncthreads();
            if (tid < NQ)
                g_qkv[((h * 3 + p) * BT + bt) * NQ + tid] = red[tid];
            __syncthreads();
        }
    }
}

// ---------------- attention (last row only) + MLP ----------------
__global__ void qtf_head(
    const float* __restrict__ W1, const float* __restrict__ b1,
    const float* __restrict__ W2, const float* __restrict__ b2,
    float* __restrict__ out)
{
    const int b = blockIdx.x;
    const int s = threadIdx.x;   // 64 threads, one per source position
    __shared__ float feat[24];
    __shared__ float redm[2], reds[2];
    __shared__ float hdn[48];
    if (s < 24) feat[s] = 0.0f;
    __syncthreads();

    for (int h = 0; h < 2; h++) {
        const float* Q = &g_qkv[((h * 3 + 0) * BT + b * SEQ + (SEQ - 1)) * NQ];
        const float* K = &g_qkv[((h * 3 + 1) * BT + b * SEQ) * NQ];
        const float* V = &g_qkv[((h * 3 + 2) * BT + b * SEQ) * NQ];
        float sc = 0.0f;
        #pragma unroll
        for (int q = 0; q < NQ; q++) sc += Q[q] * K[s * NQ + q];
        sc *= 0.28867513459481287f;   // 1/sqrt(12)
        // mask row t=63 is all zeros -> no masking
        float m = sc;
        for (int off = 16; off; off >>= 1)
            m = fmaxf(m, __shfl_xor_sync(0xffffffffu, m, off));
        int w = s >> 5;
        if ((s & 31) == 0) redm[w] = m;
        __syncthreads();
        m = fmaxf(redm[0], redm[1]);
        float e = expf(sc - m);
        float sum = e;
        for (int off = 16; off; off >>= 1)
            sum += __shfl_xor_sync(0xffffffffu, sum, off);
        if ((s & 31) == 0) reds[w] = sum;
        __syncthreads();
        sum = reds[0] + reds[1];
        float wgt = e / sum;
        #pragma unroll
        for (int d = 0; d < NQ; d++) {
            float v = wgt * V[s * NQ + d];
            for (int off = 16; off; off >>= 1)
                v += __shfl_xor_sync(0xffffffffu, v, off);
            if ((s & 31) == 0) atomicAdd(&feat[h * NQ + d], v);
        }
        __syncthreads();
    }

    if (s < 48) {
        float a = b1[s];
        #pragma unroll
        for (int i = 0; i < 24; i++) a += feat[i] * W1[i * 48 + s];
        hdn[s] = 0.5f * a * (1.0f + erff(a * 0.7071067811865476f));  // exact gelu
    }
    __syncthreads();
    if (s < 4) {
        float a = b2[s];
        #pragma unroll
        for (int j = 0; j < 48; j++) a += hdn[j] * W2[j * 4 + s];
        out[b * 4 + s] = a;
    }
}

extern "C" void kernel_launch(void* const* d_in, const int* in_sizes, int n_in,
                              void* d_out, int out_size)
{
    const float* seq   = (const float*)d_in[0];
    const float* resp  = (const float*)d_in[1];
    const float* headp = (const float*)d_in[2];
    const float* W1    = (const float*)d_in[3];
    const float* b1    = (const float*)d_in[4];
    const float* W2    = (const float*)d_in[5];
    const float* b2    = (const float*)d_in[6];
    float* out = (float*)d_out;

    size_t shbytes = 2 * DIM * sizeof(float2);   // 64 KB
    cudaFuncSetAttribute(qtf_main, cudaFuncAttributeMaxDynamicSharedMemorySize, (int)shbytes);

    qtf_main<<<BT, NTHR, shbytes>>>(seq, resp, headp);
    qtf_head<<<BATCH, 64>>>(W1, b1, W2, b2, out);
}

// round 3
// speedup vs baseline: 2.7308x; 2.7308x over previous
#include <cuda_runtime.h>
#include <math.h>

#define NQ    12
#define DIM   4096
#define BATCH 8
#define SEQ   64
#define BT    (BATCH*SEQ)
#define NTHR  256
#define KREG  16

#define PI_D 3.14159265358979323846

// QKV features [head*3+proj][bt][12]
__device__ float  g_qkv[6*BT*NQ];
// precomputed gate matrices (same for all CTAs)
__device__ float2 g_res[36*4];      // reservoir u3 gates: [layer*12+i][4]
__device__ float2 g_proj[6*24*4];   // projection ryrz gates: [(h*3+p)*24 + layer*12+i][4]

// ---------------- complex helpers ----------------
__device__ __forceinline__ float2 cmul(float2 a, float2 b) {
    return make_float2(a.x*b.x - a.y*b.y, a.x*b.y + a.y*b.x);
}
__device__ __forceinline__ float2 cfma2(float2 ca, float2 s, float2 cb, float2 o) {
    float2 r;
    r.x = ca.x*s.x - ca.y*s.y + cb.x*o.x - cb.y*o.y;
    r.y = ca.x*s.y + ca.y*s.x + cb.x*o.y + cb.y*o.x;
    return r;
}

// ---------------- setup: precompute gate matrices ----------------
__global__ void qtf_setup(const float* __restrict__ resp, const float* __restrict__ headp)
{
    int j = threadIdx.x;
    if (j < 36) {
        float tt = resp[j*3+0], pp = resp[j*3+1], ll = resp[j*3+2];
        float st_, ct, sl, cl, sp, cp, spl, cpl;
        sincosf(0.5f*tt, &st_, &ct);
        sincosf(ll, &sl, &cl);
        sincosf(pp, &sp, &cp);
        sincosf(pp+ll, &spl, &cpl);
        g_res[j*4+0] = make_float2(ct, 0.f);
        g_res[j*4+1] = make_float2(-cl*st_, -sl*st_);
        g_res[j*4+2] = make_float2( cp*st_,  sp*st_);
        g_res[j*4+3] = make_float2(cpl*ct,  spl*ct);
    }
    if (j >= 64 && j < 64 + 144) {
        int s  = j - 64;
        int hp = s / 24, gi = s % 24;
        const float* pars = headp + hp*48;
        float th = pars[gi*2], ph = pars[gi*2+1];
        float sn, cs, sh, ch;
        sincosf(0.5f*th, &sn, &cs);
        sincosf(0.5f*ph, &sh, &ch);
        g_proj[s*4+0] = make_float2( cs*ch, -cs*sh);
        g_proj[s*4+1] = make_float2(-sn*ch,  sn*sh);
        g_proj[s*4+2] = make_float2( sn*ch,  sn*sh);
        g_proj[s*4+3] = make_float2( cs*ch,  cs*sh);
    }
}

// ---------------- gate on qubit i ----------------
__device__ __forceinline__ void apply_gate_i(float2 st[KREG], float2* work, int tid, int i,
                                             float2 g00, float2 g01, float2 g10, float2 g11)
{
    if (i < 5) {
        // lane-bit qubit: shuffle exchange
        unsigned lm = 1u << i;
        int hi = (tid >> i) & 1;
        float2 ca = hi ? g11 : g00;
        float2 cb = hi ? g10 : g01;
        #pragma unroll
        for (int k = 0; k < KREG; k++) {
            float2 o;
            o.x = __shfl_xor_sync(0xffffffffu, st[k].x, lm);
            o.y = __shfl_xor_sync(0xffffffffu, st[k].y, lm);
            st[k] = cfma2(ca, st[k], cb, o);
        }
    } else if (i < 8) {
        // warp-bit qubit: smem exchange
        __syncthreads();
        #pragma unroll
        for (int k = 0; k < KREG; k++) work[(k<<8) | tid] = st[k];
        __syncthreads();
        int pt = tid ^ (1 << i);
        int hi = (tid >> i) & 1;
        float2 ca = hi ? g11 : g00;
        float2 cb = hi ? g10 : g01;
        #pragma unroll
        for (int k = 0; k < KREG; k++) {
            float2 o = work[(k<<8) | pt];
            st[k] = cfma2(ca, st[k], cb, o);
        }
    } else {
        // local-bit qubit: pure register math
        int m = 1 << (i - 8);
        #pragma unroll
        for (int k = 0; k < KREG; k++) {
            if (!(k & m)) {
                float2 s0 = st[k], s1 = st[k | m];
                st[k]     = cfma2(g00, s0, g01, s1);
                st[k | m] = cfma2(g10, s0, g11, s1);
            }
        }
    }
}

// projection CX ladder (11 CXs composed): one gather pass.
__device__ __forceinline__ void perm_ladder(float2 st[KREG], float2* work, int tid)
{
    __syncthreads();
    #pragma unroll
    for (int k = 0; k < KREG; k++) work[(k<<8) | tid] = st[k];
    __syncthreads();
    #pragma unroll
    for (int k = 0; k < KREG; k++) {
        int d = (k<<8) | tid;
        int s = ((d ^ (d << 1)) & 0xFFE) | (d & 1);
        st[k] = work[s];
    }
}

extern __shared__ float2 smem[];   // [0..4095] work, [4096..8191] enc snapshot

__global__ void __launch_bounds__(NTHR) qtf_main(const float* __restrict__ seq)
{
    float2* work = smem;
    float2* encs = smem + DIM;
    const int tid = threadIdx.x;
    const int bt  = blockIdx.x;
    const int t   = bt & (SEQ - 1);
    const float x = seq[bt];

    float2 st[KREG];

    // ======== encode: product state with folded ladder+ring permutation G ========
    {
        float2 F = make_float2(1.0f, 0.0f);
        float2 wv[6][2];   // qubits 0,1,8,9,10,11
        #pragma unroll
        for (int i = 0; i < NQ; i++) {
            float th = x * (float)(PI_D * (double)(i + 1) / 12.0);
            float ph = x * (float)(PI_D / (double)(i + 1));
            float s, c, sh, ch;
            __sincosf(0.5f*th, &s, &c);
            __sincosf(0.5f*ph, &sh, &ch);
            float am = (c - s) * 0.70710678118654752f;
            float ap = (c + s) * 0.70710678118654752f;
            float2 v0 = make_float2(am*ch, -am*sh);
            float2 v1 = make_float2(ap*ch,  ap*sh);
            if (i >= 2 && i <= 7) {
                int bit = ((tid >> (i-1)) ^ (tid >> i)) & 1;
                F = cmul(F, bit ? v1 : v0);
            } else {
                int vi = (i < 2) ? i : (i - 6);
                wv[vi][0] = v0; wv[vi][1] = v1;
            }
        }
        int a0 = tid & 1, a1 = (tid >> 1) & 1, a7 = (tid >> 7) & 1;
        #pragma unroll
        for (int k = 0; k < KREG; k++) {
            int k0 = k & 1, k1 = (k >> 1) & 1, k2 = (k >> 2) & 1, k3 = (k >> 3) & 1;
            float2 a = cmul(F, (a0 ^ k3)      ? wv[0][1] : wv[0][0]);
            a = cmul(a, (a0 ^ a1 ^ k3) ? wv[1][1] : wv[1][0]);
            a = cmul(a, (a7 ^ k0)      ? wv[2][1] : wv[2][0]);
            a = cmul(a, (k0 ^ k1)      ? wv[3][1] : wv[3][0]);
            a = cmul(a, (k1 ^ k2)      ? wv[4][1] : wv[4][0]);
            a = cmul(a, (k2 ^ k3)      ? wv[5][1] : wv[5][0]);
            st[k] = a;
        }
    }

    // ======== reservoir: 3 layers of 12 u3 gates + CZ + CX(0,11) ========
    for (int layer = 0; layer < 3; layer++) {
        const float2* gl = g_res + layer * 12 * 4;
        #pragma unroll
        for (int i = 0; i < NQ; i++) {
            float2 g00 = gl[i*4+0], g01 = gl[i*4+1], g10 = gl[i*4+2], g11 = gl[i*4+3];
            apply_gate_i(st, work, tid, i, g00, g01, g10, g11);
        }
        unsigned mask = (layer & 1) ? 0x2AAu : 0x555u;
        #pragma unroll
        for (int k = 0; k < KREG; k++) {
            int d = (k<<8) | tid;
            unsigned m = ((unsigned)d & ((unsigned)d >> 1)) & mask;
            if (__popc(m) & 1) { st[k].x = -st[k].x; st[k].y = -st[k].y; }
        }
        if (tid & 1) {
            #pragma unroll
            for (int k = 0; k < 8; k++) {
                float2 tmp = st[k]; st[k] = st[k+8]; st[k+8] = tmp;
            }
        }
    }

    // snapshot encoded state (own cells only, no barrier needed)
    #pragma unroll
    for (int k = 0; k < KREG; k++) encs[(k<<8) | tid] = st[k];

    // ======== projections (Q only at t = SEQ-1) ========
    __shared__ float red[NQ];
    const bool lastt = (t == SEQ - 1);
    bool first = true;
    for (int h = 0; h < 2; h++) {
        for (int p = 0; p < 3; p++) {
            if (p == 0 && !lastt) continue;
            if (!first) {
                #pragma unroll
                for (int k = 0; k < KREG; k++) st[k] = encs[(k<<8) | tid];
            }
            first = false;
            const float2* gp = g_proj + (h*3 + p) * 24 * 4;
            for (int layer = 0; layer < 2; layer++) {
                #pragma unroll
                for (int i = 0; i < NQ; i++) {
                    const float2* g = gp + (layer*12 + i)*4;
                    apply_gate_i(st, work, tid, i, g[0], g[1], g[2], g[3]);
                }
                perm_ladder(st, work, tid);
            }
            // ---- feature extraction: <Z_q>, sign bit = 11-q ----
            float S = 0.f, T0 = 0.f, T1 = 0.f, T2 = 0.f, T3 = 0.f;
            #pragma unroll
            for (int k = 0; k < KREG; k++) {
                float p2 = st[k].x*st[k].x + st[k].y*st[k].y;
                S += p2;
                if (k & 1) T0 += p2;
                if (k & 2) T1 += p2;
                if (k & 4) T2 += p2;
                if (k & 8) T3 += p2;
            }
            float acc[NQ];
            acc[0] = S - 2.f*T3;   // bit11 = k3
            acc[1] = S - 2.f*T2;   // bit10 = k2
            acc[2] = S - 2.f*T1;   // bit9  = k1
            acc[3] = S - 2.f*T0;   // bit8  = k0
            #pragma unroll
            for (int q = 4; q < NQ; q++)
                acc[q] = ((tid >> (11 - q)) & 1) ? -S : S;
            #pragma unroll
            for (int q = 0; q < NQ; q++) {
                float v = acc[q];
                #pragma unroll
                for (int o = 16; o; o >>= 1)
                    v += __shfl_xor_sync(0xffffffffu, v, o);
                acc[q] = v;
            }
            if (tid < NQ) red[tid] = 0.f;
            __syncthreads();
            if ((tid & 31) == 0) {
                #pragma unroll
                for (int q = 0; q < NQ; q++) atomicAdd(&red[q], acc[q]);
            }
            __syncthreads();
            if (tid < NQ)
                g_qkv[((h*3 + p)*BT + bt)*NQ + tid] = red[tid];
            __syncthreads();
        }
    }
}

// ---------------- attention (last row only) + MLP ----------------
__global__ void qtf_head(
    const float* __restrict__ W1, const float* __restrict__ b1,
    const float* __restrict__ W2, const float* __restrict__ b2,
    float* __restrict__ out)
{
    const int b = blockIdx.x;
    const int s = threadIdx.x;   // 64 threads
    __shared__ float feat[24];
    __shared__ float redm[2], reds[2];
    __shared__ float hdn[48];
    if (s < 24) feat[s] = 0.0f;
    __syncthreads();

    for (int h = 0; h < 2; h++) {
        const float* Q = &g_qkv[((h*3 + 0)*BT + b*SEQ + (SEQ-1))*NQ];
        const float* K = &g_qkv[((h*3 + 1)*BT + b*SEQ)*NQ];
        const float* V = &g_qkv[((h*3 + 2)*BT + b*SEQ)*NQ];
        float sc = 0.0f;
        #pragma unroll
        for (int q = 0; q < NQ; q++) sc += Q[q] * K[s*NQ + q];
        sc *= 0.28867513459481287f;   // 1/sqrt(12)
        float m = sc;
        for (int off = 16; off; off >>= 1)
            m = fmaxf(m, __shfl_xor_sync(0xffffffffu, m, off));
        int w = s >> 5;
        if ((s & 31) == 0) redm[w] = m;
        __syncthreads();
        m = fmaxf(redm[0], redm[1]);
        float e = expf(sc - m);
        float sum = e;
        for (int off = 16; off; off >>= 1)
            sum += __shfl_xor_sync(0xffffffffu, sum, off);
        if ((s & 31) == 0) reds[w] = sum;
        __syncthreads();
        sum = reds[0] + reds[1];
        float wgt = e / sum;
        #pragma unroll
        for (int d = 0; d < NQ; d++) {
            float v = wgt * V[s*NQ + d];
            for (int off = 16; off; off >>= 1)
                v += __shfl_xor_sync(0xffffffffu, v, off);
            if ((s & 31) == 0) atomicAdd(&feat[h*NQ + d], v);
        }
        __syncthreads();
    }

    if (s < 48) {
        float a = b1[s];
        #pragma unroll
        for (int i = 0; i < 24; i++) a += feat[i] * W1[i*48 + s];
        hdn[s] = 0.5f * a * (1.0f + erff(a * 0.7071067811865476f));
    }
    __syncthreads();
    if (s < 4) {
        float a = b2[s];
        #pragma unroll
        for (int j = 0; j < 48; j++) a += hdn[j] * W2[j*4 + s];
        out[b*4 + s] = a;
    }
}

extern "C" void kernel_launch(void* const* d_in, const int* in_sizes, int n_in,
                              void* d_out, int out_size)
{
    const float* seq   = (const float*)d_in[0];
    const float* resp  = (const float*)d_in[1];
    const float* headp = (const float*)d_in[2];
    const float* W1    = (const float*)d_in[3];
    const float* b1    = (const float*)d_in[4];
    const float* W2    = (const float*)d_in[5];
    const float* b2    = (const float*)d_in[6];
    float* out = (float*)d_out;

    size_t shbytes = 2 * DIM * sizeof(float2);   // 64 KB
    cudaFuncSetAttribute(qtf_main, cudaFuncAttributeMaxDynamicSharedMemorySize, (int)shbytes);

    qtf_setup<<<1, 256>>>(resp, headp);
    qtf_main<<<BT, NTHR, shbytes>>>(seq);
    qtf_head<<<BATCH, 64>>>(W1, b1, W2, b2, out);
}

// round 4
// speedup vs baseline: 3.1081x; 1.1382x over previous
#include <cuda_runtime.h>
#include <math.h>

#define NQ    12
#define DIM   4096
#define BATCH 8
#define SEQ   64
#define BT    (BATCH*SEQ)
#define NTHR  256
#define KREG  16

#define PI_D 3.14159265358979323846

// QKV features [head*3+proj][bt][12]
__device__ float  g_qkv[6*BT*NQ];
// precomputed gate matrices (same for all CTAs)
__device__ float2 g_res[36*4];      // reservoir u3 gates: [layer*12+i][4]
__device__ float2 g_proj[6*24*4];   // projection ryrz gates

// ---------------- complex helpers ----------------
__device__ __forceinline__ float2 cmul(float2 a, float2 b) {
    return make_float2(a.x*b.x - a.y*b.y, a.x*b.y + a.y*b.x);
}
__device__ __forceinline__ float2 cfma2(float2 ca, float2 s, float2 cb, float2 o) {
    float2 r;
    r.x = ca.x*s.x - ca.y*s.y + cb.x*o.x - cb.y*o.y;
    r.y = ca.x*s.y + ca.y*s.x + cb.x*o.y + cb.y*o.x;
    return r;
}

// ---------------- setup: precompute gate matrices ----------------
__global__ void qtf_setup(const float* __restrict__ resp, const float* __restrict__ headp)
{
    int j = threadIdx.x;
    if (j < 36) {
        float tt = resp[j*3+0], pp = resp[j*3+1], ll = resp[j*3+2];
        float st_, ct, sl, cl, sp, cp, spl, cpl;
        sincosf(0.5f*tt, &st_, &ct);
        sincosf(ll, &sl, &cl);
        sincosf(pp, &sp, &cp);
        sincosf(pp+ll, &spl, &cpl);
        g_res[j*4+0] = make_float2(ct, 0.f);
        g_res[j*4+1] = make_float2(-cl*st_, -sl*st_);
        g_res[j*4+2] = make_float2( cp*st_,  sp*st_);
        g_res[j*4+3] = make_float2(cpl*ct,  spl*ct);
    }
    if (j >= 64 && j < 64 + 144) {
        int s  = j - 64;
        int hp = s / 24, gi = s % 24;
        const float* pars = headp + hp*48;
        float th = pars[gi*2], ph = pars[gi*2+1];
        float sn, cs, sh, ch;
        sincosf(0.5f*th, &sn, &cs);
        sincosf(0.5f*ph, &sh, &ch);
        g_proj[s*4+0] = make_float2( cs*ch, -cs*sh);
        g_proj[s*4+1] = make_float2(-sn*ch,  sn*sh);
        g_proj[s*4+2] = make_float2( sn*ch,  sn*sh);
        g_proj[s*4+3] = make_float2( cs*ch,  cs*sh);
    }
}

// ---------------- layouts ----------------
// A: amp d = (k<<8) | tid           (local bits = qubits 8..11)
// B: amp d = (tid&31) | ((k&7)<<5) | ((tid>>5)<<8) | ((k>>3)<<11)
//                                   (local bits = qubits 5,6,7,11)
__device__ __forceinline__ int addrA(int tid, int k) { return (k<<8) | tid; }
__device__ __forceinline__ int addrB(int tid, int k) {
    return (tid & 31) | ((k & 7) << 5) | ((tid >> 5) << 8) | ((k >> 3) << 11);
}
// projection CX-ladder gather source
__device__ __forceinline__ int ladd(int d) {
    return ((d ^ (d << 1)) & 0xFFE) | (d & 1);
}

// ---------------- gate primitives ----------------
__device__ __forceinline__ void gate_lane(float2 st[KREG], int tid, int i, const float2* g)
{
    unsigned lm = 1u << i;
    int hi = (tid >> i) & 1;
    float2 ca = hi ? g[3] : g[0];
    float2 cb = hi ? g[2] : g[1];
    #pragma unroll
    for (int k = 0; k < KREG; k++) {
        float2 o;
        o.x = __shfl_xor_sync(0xffffffffu, st[k].x, lm);
        o.y = __shfl_xor_sync(0xffffffffu, st[k].y, lm);
        st[k] = cfma2(ca, st[k], cb, o);
    }
}
__device__ __forceinline__ void gate_local(float2 st[KREG], int m, const float2* g)
{
    float2 g00 = g[0], g01 = g[1], g10 = g[2], g11 = g[3];
    #pragma unroll
    for (int k = 0; k < KREG; k++) {
        if (!(k & m)) {
            float2 s0 = st[k], s1 = st[k | m];
            st[k]     = cfma2(g00, s0, g01, s1);
            st[k | m] = cfma2(g10, s0, g11, s1);
        }
    }
}
// CX(0,11): identical in both layouts (bit0 = tid&1, bit11 = k bit 3)
__device__ __forceinline__ void cx011(float2 st[KREG], int tid)
{
    if (tid & 1) {
        #pragma unroll
        for (int k = 0; k < 8; k++) {
            float2 tmp = st[k]; st[k] = st[k+8]; st[k+8] = tmp;
        }
    }
}
__device__ __forceinline__ void czA(float2 st[KREG], int tid, unsigned mask)
{
    #pragma unroll
    for (int k = 0; k < KREG; k++) {
        unsigned d = (unsigned)addrA(tid, k);
        if (__popc((d & (d >> 1)) & mask) & 1) { st[k].x = -st[k].x; st[k].y = -st[k].y; }
    }
}
__device__ __forceinline__ void czB(float2 st[KREG], int tid, unsigned mask)
{
    #pragma unroll
    for (int k = 0; k < KREG; k++) {
        unsigned d = (unsigned)addrB(tid, k);
        if (__popc((d & (d >> 1)) & mask) & 1) { st[k].x = -st[k].x; st[k].y = -st[k].y; }
    }
}

// ---------------- layout roundtrips ----------------
__device__ __forceinline__ void rtAB(float2 st[KREG], float2* work, int tid, bool ladder)
{
    __syncthreads();
    #pragma unroll
    for (int k = 0; k < KREG; k++) work[addrA(tid, k)] = st[k];
    __syncthreads();
    #pragma unroll
    for (int k = 0; k < KREG; k++) {
        int D = addrB(tid, k);
        st[k] = work[ladder ? ladd(D) : D];
    }
}
__device__ __forceinline__ void rtBA(float2 st[KREG], float2* work, int tid)
{
    __syncthreads();
    #pragma unroll
    for (int k = 0; k < KREG; k++) work[addrB(tid, k)] = st[k];
    __syncthreads();
    #pragma unroll
    for (int k = 0; k < KREG; k++) st[k] = work[addrA(tid, k)];
}

extern __shared__ float2 smem[];   // [0..4095] work, [4096..8191] enc snapshot, [8192..8911] gates

__global__ void __launch_bounds__(NTHR) qtf_main(const float* __restrict__ seq)
{
    float2* work    = smem;
    float2* encs    = smem + DIM;
    float2* sm_res  = smem + 2*DIM;          // 144 float2
    float2* sm_proj = smem + 2*DIM + 144;    // 576 float2
    const int tid = threadIdx.x;
    const int bt  = blockIdx.x;
    const int t   = bt & (SEQ - 1);
    const float x = seq[bt];

    // cache gate matrices in smem
    for (int j = tid; j < 144; j += NTHR) sm_res[j]  = g_res[j];
    for (int j = tid; j < 576; j += NTHR) sm_proj[j] = g_proj[j];

    float2 st[KREG];

    // ======== encode: product state with folded ladder+ring perm (layout A) ========
    {
        float2 F = make_float2(1.0f, 0.0f);
        float2 wv[6][2];   // qubits 0,1,8,9,10,11
        #pragma unroll
        for (int i = 0; i < NQ; i++) {
            float th = x * (float)(PI_D * (double)(i + 1) / 12.0);
            float ph = x * (float)(PI_D / (double)(i + 1));
            float s, c, sh, ch;
            __sincosf(0.5f*th, &s, &c);
            __sincosf(0.5f*ph, &sh, &ch);
            float am = (c - s) * 0.70710678118654752f;
            float ap = (c + s) * 0.70710678118654752f;
            float2 v0 = make_float2(am*ch, -am*sh);
            float2 v1 = make_float2(ap*ch,  ap*sh);
            if (i >= 2 && i <= 7) {
                int bit = ((tid >> (i-1)) ^ (tid >> i)) & 1;
                F = cmul(F, bit ? v1 : v0);
            } else {
                int vi = (i < 2) ? i : (i - 6);
                wv[vi][0] = v0; wv[vi][1] = v1;
            }
        }
        int a0 = tid & 1, a1 = (tid >> 1) & 1, a7 = (tid >> 7) & 1;
        #pragma unroll
        for (int k = 0; k < KREG; k++) {
            int k0 = k & 1, k1 = (k >> 1) & 1, k2 = (k >> 2) & 1, k3 = (k >> 3) & 1;
            float2 a = cmul(F, (a0 ^ k3)      ? wv[0][1] : wv[0][0]);
            a = cmul(a, (a0 ^ a1 ^ k3) ? wv[1][1] : wv[1][0]);
            a = cmul(a, (a7 ^ k0)      ? wv[2][1] : wv[2][0]);
            a = cmul(a, (k0 ^ k1)      ? wv[3][1] : wv[3][0]);
            a = cmul(a, (k1 ^ k2)      ? wv[4][1] : wv[4][0]);
            a = cmul(a, (k2 ^ k3)      ? wv[5][1] : wv[5][0]);
            st[k] = a;
        }
    }
    __syncthreads();  // gate smem copy complete

    // ======== reservoir: 1 roundtrip per layer, alternating layouts ========
    #define RG(l,i) (sm_res + ((l)*12 + (i))*4)
    // layer 0 (A -> B)
    {
        #pragma unroll
        for (int i = 0; i < 5; i++) gate_lane(st, tid, i, RG(0,i));
        gate_local(st, 1, RG(0,8)); gate_local(st, 2, RG(0,9));
        gate_local(st, 4, RG(0,10)); gate_local(st, 8, RG(0,11));
        rtAB(st, work, tid, false);
        gate_local(st, 1, RG(0,5)); gate_local(st, 2, RG(0,6)); gate_local(st, 4, RG(0,7));
        czB(st, tid, 0x555u); cx011(st, tid);
    }
    // layer 1 (B -> A)
    {
        #pragma unroll
        for (int i = 0; i < 5; i++) gate_lane(st, tid, i, RG(1,i));
        gate_local(st, 1, RG(1,5)); gate_local(st, 2, RG(1,6));
        gate_local(st, 4, RG(1,7)); gate_local(st, 8, RG(1,11));
        rtBA(st, work, tid);
        gate_local(st, 1, RG(1,8)); gate_local(st, 2, RG(1,9)); gate_local(st, 4, RG(1,10));
        czA(st, tid, 0x2AAu); cx011(st, tid);
    }
    // layer 2 (A -> B)
    {
        #pragma unroll
        for (int i = 0; i < 5; i++) gate_lane(st, tid, i, RG(2,i));
        gate_local(st, 1, RG(2,8)); gate_local(st, 2, RG(2,9));
        gate_local(st, 4, RG(2,10)); gate_local(st, 8, RG(2,11));
        rtAB(st, work, tid, false);
        gate_local(st, 1, RG(2,5)); gate_local(st, 2, RG(2,6)); gate_local(st, 4, RG(2,7));
        czB(st, tid, 0x555u); cx011(st, tid);
    }

    // snapshot encoded state (layout B; own cells only, no barrier needed)
    #pragma unroll
    for (int k = 0; k < KREG; k++) encs[(k<<8) | tid] = st[k];

    // ======== projections (Q only at t = SEQ-1); 3 roundtrips each ========
    __shared__ float red[NQ];
    const bool lastt = (t == SEQ - 1);
    bool first = true;
    for (int h = 0; h < 2; h++) {
        for (int p = 0; p < 3; p++) {
            if (p == 0 && !lastt) continue;
            if (!first) {
                #pragma unroll
                for (int k = 0; k < KREG; k++) st[k] = encs[(k<<8) | tid];
            }
            first = false;
            const float2* gp = sm_proj + (h*3 + p) * 24 * 4;
            #define PG(l,i) (gp + ((l)*12 + (i))*4)
            // attn layer 0 (state in B)
            #pragma unroll
            for (int i = 0; i < 5; i++) gate_lane(st, tid, i, PG(0,i));
            gate_local(st, 1, PG(0,5)); gate_local(st, 2, PG(0,6));
            gate_local(st, 4, PG(0,7)); gate_local(st, 8, PG(0,11));
            rtBA(st, work, tid);
            gate_local(st, 1, PG(0,8)); gate_local(st, 2, PG(0,9)); gate_local(st, 4, PG(0,10));
            rtAB(st, work, tid, true);   // ladder folded into gather
            // attn layer 1 (state in B)
            #pragma unroll
            for (int i = 0; i < 5; i++) gate_lane(st, tid, i, PG(1,i));
            gate_local(st, 1, PG(1,5)); gate_local(st, 2, PG(1,6));
            gate_local(st, 4, PG(1,7)); gate_local(st, 8, PG(1,11));
            rtBA(st, work, tid);
            gate_local(st, 1, PG(1,8)); gate_local(st, 2, PG(1,9)); gate_local(st, 4, PG(1,10));
            // final ladder folded into feature sign masks:
            // feats[q] = sum_d (1 - 2*parity(d & ((1<<(12-q))-1))) * p(d), layout A
            float S = 0.f, B0 = 0.f, B1 = 0.f, B2 = 0.f, B3 = 0.f;
            #pragma unroll
            for (int k = 0; k < KREG; k++) {
                float pr = st[k].x*st[k].x + st[k].y*st[k].y;
                S += pr;
                B0 += ( k        & 1) ? -pr : pr;   // parity(k&1)
                B1 += ((k^(k>>1))& 1) ? -pr : pr;   // parity(k&3)
                B2 += (__popc(k & 7) & 1) ? -pr : pr;
                B3 += (__popc(k & 15) & 1) ? -pr : pr;
            }
            float tsgn = (__popc(tid) & 1) ? -1.f : 1.f;
            float acc[NQ];
            acc[0] = tsgn * B3;
            acc[1] = tsgn * B2;
            acc[2] = tsgn * B1;
            acc[3] = tsgn * B0;
            #pragma unroll
            for (int q = 4; q < NQ; q++) {
                int mt = 0xFF >> (q - 4);
                acc[q] = (__popc(tid & mt) & 1) ? -S : S;
            }
            #pragma unroll
            for (int q = 0; q < NQ; q++) {
                float v = acc[q];
                #pragma unroll
                for (int o = 16; o; o >>= 1)
                    v += __shfl_xor_sync(0xffffffffu, v, o);
                acc[q] = v;
            }
            if (tid < NQ) red[tid] = 0.f;
            __syncthreads();
            if ((tid & 31) == 0) {
                #pragma unroll
                for (int q = 0; q < NQ; q++) atomicAdd(&red[q], acc[q]);
            }
            __syncthreads();
            if (tid < NQ)
                g_qkv[((h*3 + p)*BT + bt)*NQ + tid] = red[tid];
            __syncthreads();
        }
    }
}

// ---------------- attention (last row only, both heads parallel) + MLP ----------------
__global__ void qtf_head(
    const float* __restrict__ W1, const float* __restrict__ b1,
    const float* __restrict__ W2, const float* __restrict__ b2,
    float* __restrict__ out)
{
    const int b   = blockIdx.x;
    const int tid = threadIdx.x;       // 128
    const int h   = tid >> 6;
    const int s   = tid & 63;
    __shared__ float feat[24];
    __shared__ float redm[2][2], reds[2][2];
    __shared__ float hdn[48];
    if (tid < 24) feat[tid] = 0.0f;
    __syncthreads();

    const float* Q = &g_qkv[((h*3 + 0)*BT + b*SEQ + (SEQ-1))*NQ];
    const float* K = &g_qkv[((h*3 + 1)*BT + b*SEQ)*NQ];
    const float* V = &g_qkv[((h*3 + 2)*BT + b*SEQ)*NQ];
    float sc = 0.0f;
    #pragma unroll
    for (int q = 0; q < NQ; q++) sc += Q[q] * K[s*NQ + q];
    sc *= 0.28867513459481287f;   // 1/sqrt(12)
    float m = sc;
    #pragma unroll
    for (int off = 16; off; off >>= 1)
        m = fmaxf(m, __shfl_xor_sync(0xffffffffu, m, off));
    int w = s >> 5;
    if ((s & 31) == 0) redm[h][w] = m;
    __syncthreads();
    m = fmaxf(redm[h][0], redm[h][1]);
    float e = expf(sc - m);
    float sum = e;
    #pragma unroll
    for (int off = 16; off; off >>= 1)
        sum += __shfl_xor_sync(0xffffffffu, sum, off);
    if ((s & 31) == 0) reds[h][w] = sum;
    __syncthreads();
    sum = reds[h][0] + reds[h][1];
    float wgt = e / sum;
    #pragma unroll
    for (int d = 0; d < NQ; d++) {
        float v = wgt * V[s*NQ + d];
        #pragma unroll
        for (int off = 16; off; off >>= 1)
            v += __shfl_xor_sync(0xffffffffu, v, off);
        if ((s & 31) == 0) atomicAdd(&feat[h*NQ + d], v);
    }
    __syncthreads();

    if (tid < 48) {
        float a = b1[tid];
        #pragma unroll
        for (int i = 0; i < 24; i++) a += feat[i] * W1[i*48 + tid];
        hdn[tid] = 0.5f * a * (1.0f + erff(a * 0.7071067811865476f));
    }
    __syncthreads();
    if (tid < 4) {
        float a = b2[tid];
        #pragma unroll
        for (int j = 0; j < 48; j++) a += hdn[j] * W2[j*4 + tid];
        out[b*4 + tid] = a;
    }
}

extern "C" void kernel_launch(void* const* d_in, const int* in_sizes, int n_in,
                              void* d_out, int out_size)
{
    const float* seq   = (const float*)d_in[0];
    const float* resp  = (const float*)d_in[1];
    const float* headp = (const float*)d_in[2];
    const float* W1    = (const float*)d_in[3];
    const float* b1    = (const float*)d_in[4];
    const float* W2    = (const float*)d_in[5];
    const float* b2    = (const float*)d_in[6];
    float* out = (float*)d_out;

    size_t shbytes = (2*DIM + 720) * sizeof(float2);   // work + encs + gate cache
    cudaFuncSetAttribute(qtf_main, cudaFuncAttributeMaxDynamicSharedMemorySize, (int)shbytes);

    qtf_setup<<<1, 256>>>(resp, headp);
    qtf_main<<<BT, NTHR, shbytes>>>(seq);
    qtf_head<<<BATCH, 128>>>(W1, b1, W2, b2, out);
}